// round 16
// baseline (speedup 1.0000x reference)
#include <cuda_runtime.h>
#include <cuda_bf16.h>
#include <cstdint>

#define B_DIM 4
#define L_DIM 512
#define D_DIM 768
#define KWIN  10
#define PDIM  50
#define RDIM  1586      // 2*768 + 50
#define RDIMP 1588      // padded to 16B multiple (397 float4)
#define NREL  21
#define NPAIR 10642
#define NEXT  3172      // concatenated A|C output columns
#define NEXTP 3200      // padded to 128-multiple
#define NCHUNK 36       // 3 * 768 / 64
#define NCH4  397       // RDIMP / 4

#define N_MMA_ITEMS  400               // 16 m-tiles x 25 n-tiles
#define N_PAIR_ITEMS (B_DIM * L_DIM)   // 2048
#define N_ITEMS      (N_MMA_ITEMS + N_PAIR_ITEMS)
#define GRID_FUSED   296               // 2 CTAs per SM on 148 SMs

// ------------------------- device scratch (no runtime alloc allowed) ------
__device__ __align__(16) float g_A  [B_DIM * L_DIM * RDIMP];
__device__ __align__(16) float g_C  [B_DIM * L_DIM * RDIMP];
__device__ __align__(16) float g_E2 [NREL * RDIMP];
__device__ __align__(16) float g_W2p[RDIMP];
__device__ __align__(16) __nv_bfloat16 g_Xhi[B_DIM * L_DIM * D_DIM];
__device__ __align__(16) __nv_bfloat16 g_Xlo[B_DIM * L_DIM * D_DIM];
__device__ __align__(16) __nv_bfloat16 g_Bhi[NEXTP * D_DIM];
__device__ __align__(16) __nv_bfloat16 g_Blo[NEXTP * D_DIM];
__device__ int g_next;            // work-queue head (reset in k_prep)
__device__ int g_mtile[16];       // per-m-tile n-completion counters

// ------------------------- helpers ----------------------------------------
__device__ __forceinline__ uint32_t smem_u32(const void* p) {
    uint32_t a;
    asm("{ .reg .u64 t; cvta.to.shared.u64 t, %1; cvt.u32.u64 %0, t; }" : "=r"(a) : "l"(p));
    return a;
}
__device__ __forceinline__ uint32_t swz(uint32_t b) { return b ^ ((b >> 3) & 0x70); }

__device__ __forceinline__ void cp16(uint32_t saddr, const void* gaddr) {
    asm volatile("cp.async.cg.shared.global [%0], [%1], 16;" :: "r"(saddr), "l"(gaddr));
}
__device__ __forceinline__ void ldsm_x4(uint32_t* r, uint32_t addr) {
    asm volatile("ldmatrix.sync.aligned.m8n8.x4.shared.b16 {%0,%1,%2,%3}, [%4];"
                 : "=r"(r[0]), "=r"(r[1]), "=r"(r[2]), "=r"(r[3]) : "r"(addr));
}
__device__ __forceinline__ void mma16816(float* d, const uint32_t* a, uint32_t b0, uint32_t b1) {
    asm volatile(
        "mma.sync.aligned.m16n8k16.row.col.f32.bf16.bf16.f32 "
        "{%0,%1,%2,%3}, {%4,%5,%6,%7}, {%8,%9}, {%0,%1,%2,%3};"
        : "+f"(d[0]), "+f"(d[1]), "+f"(d[2]), "+f"(d[3])
        : "r"(a[0]), "r"(a[1]), "r"(a[2]), "r"(a[3]), "r"(b0), "r"(b1));
}

__device__ __forceinline__ int pair_offset(int i) {
    if (i <= KWIN) return i * (KWIN + 1) + (i * (i - 1)) / 2;
    int off = 155 + (i - KWIN) * (2 * KWIN + 1);
    if (i <= L_DIM - KWIN) return off;
    int d = i - (L_DIM - KWIN);
    return off - (d * (d + 1)) / 2;
}

// ------------------------- fused precompute --------------------------------
#define PREP_X  1536
#define PREP_W  2400
#define PREP_E  147
#define PREP_W2 7
__global__ __launch_bounds__(256) void k_prep(const float* __restrict__ doc,
                                              const float* __restrict__ pos_emb,
                                              const float* __restrict__ W1,
                                              const float* __restrict__ b1,
                                              const float* __restrict__ W2) {
    const int bid = blockIdx.x;
    const int t = threadIdx.x;

    if (bid < PREP_X) {
        int idx = bid * 256 + t;       // per float4
        float4 v = reinterpret_cast<const float4*>(doc)[idx];
        __nv_bfloat16 h0 = __float2bfloat16_rn(v.x);
        __nv_bfloat16 h1 = __float2bfloat16_rn(v.y);
        __nv_bfloat16 h2 = __float2bfloat16_rn(v.z);
        __nv_bfloat16 h3 = __float2bfloat16_rn(v.w);
        __nv_bfloat162 hp0 = __nv_bfloat162(h0, h1), hp1 = __nv_bfloat162(h2, h3);
        __nv_bfloat162 lp0 = __nv_bfloat162(__float2bfloat16_rn(v.x - __bfloat162float(h0)),
                                            __float2bfloat16_rn(v.y - __bfloat162float(h1)));
        __nv_bfloat162 lp1 = __nv_bfloat162(__float2bfloat16_rn(v.z - __bfloat162float(h2)),
                                            __float2bfloat16_rn(v.w - __bfloat162float(h3)));
        reinterpret_cast<__nv_bfloat162*>(g_Xhi)[idx * 2]     = hp0;
        reinterpret_cast<__nv_bfloat162*>(g_Xhi)[idx * 2 + 1] = hp1;
        reinterpret_cast<__nv_bfloat162*>(g_Xlo)[idx * 2]     = lp0;
        reinterpret_cast<__nv_bfloat162*>(g_Xlo)[idx * 2 + 1] = lp1;
    } else if (bid < PREP_X + PREP_W) {
        __shared__ float s[32][33];
        int b2i = bid - PREP_X;
        int n0 = (b2i % 100) * 32, k0 = (b2i / 100) * 32;
        int tx = t & 31, ty = t >> 5;   // 32 x 8
#pragma unroll
        for (int r = 0; r < 4; ++r) {
            int kk = k0 + ty + r * 8;
            int nn = n0 + tx;
            float v = 0.f;
            if (nn < NEXT) {
                int col = nn < RDIM ? nn : nn - RDIM;
                int row = kk + (nn < RDIM ? 0 : D_DIM);
                v = W1[(size_t)row * RDIM + col];
            }
            s[ty + r * 8][tx] = v;
        }
        __syncthreads();
#pragma unroll
        for (int r = 0; r < 4; ++r) {
            int nl = ty + r * 8;
            int nn = n0 + nl;
            float v = s[tx][nl];
            __nv_bfloat16 h = __float2bfloat16_rn(v);
            __nv_bfloat16 l = __float2bfloat16_rn(v - __bfloat162float(h));
            g_Bhi[(size_t)nn * D_DIM + k0 + tx] = h;
            g_Blo[(size_t)nn * D_DIM + k0 + tx] = l;
        }
    } else if (bid < PREP_X + PREP_W + PREP_E) {
        __shared__ float sM[PDIM];
        int b3i = bid - PREP_X - PREP_W;       // 147 blocks
        int u  = b3i % NREL;
        int r0 = (b3i / NREL) * 256;
        if (t < PDIM) {
            float acc = 0.f;
#pragma unroll
            for (int v = 0; v < NREL; ++v) {
                float w = (float)(L_DIM - abs(v - KWIN));
                float d = (float)(u - v);
                acc += w * expf(-d * d) * pos_emb[v * PDIM + t];
            }
            sM[t] = acc;
        }
        __syncthreads();
        int r = r0 + t;
        if (r < RDIM) {
            float acc = b1[r];
#pragma unroll
            for (int p = 0; p < PDIM; ++p)
                acc += sM[p] * W1[(size_t)(2 * D_DIM + p) * RDIM + r];
            g_E2[u * RDIMP + r] = acc;
        }
    } else {
        int base = PREP_X + PREP_W + PREP_E;
        int idx = (bid - base) * 256 + t;
        if (idx < RDIMP) g_W2p[idx] = (idx < RDIM) ? W2[idx] : 0.f;
        if (bid == base) {                     // per-launch queue reset
            if (t < 16) g_mtile[t] = 0;
            if (t == 16) g_next = 0;
        }
    }
}

// ------------------------- fused mma + pair persistent kernel ---------------
#define STG_BYTES 32768                // A(16K) + B(16K) per stage
#define SMEM_TOT (3 * STG_BYTES)

__device__ void do_mma_tile(int my, int nx, char* smem) {
    const uint32_t sb = smem_u32(smem);
    const int t = threadIdx.x, w = t >> 5, lane = t & 31;
    const int n0 = nx * 128;
    const int m0 = my * 128;
    const int wm = (w >> 2) * 64;
    const int wn = (w & 3) * 32;
    float* __restrict__ gA = g_A;
    float* __restrict__ gC = g_C;

    float acc[4][4][4] = {};

    auto stage = [&](int s, int c) {
        const int seg = c / 12;
        const int kk0 = (c % 12) * 64;
        const __nv_bfloat16* Ag = (seg == 2) ? g_Xlo : g_Xhi;
        const __nv_bfloat16* Bg = (seg == 1) ? g_Blo : g_Bhi;
        const uint32_t ab = sb + s * STG_BYTES;
        const uint32_t bb = ab + 16384;
#pragma unroll
        for (int it = 0; it < 4; ++it) {
            int idx = it * 256 + t;
            int row = idx >> 3, c16 = idx & 7;
            cp16(ab + swz(row * 128 + c16 * 16),
                 Ag + (size_t)(m0 + row) * D_DIM + kk0 + c16 * 8);
        }
#pragma unroll
        for (int it = 0; it < 4; ++it) {
            int idx = it * 256 + t;
            int row = idx >> 3, c16 = idx & 7;
            cp16(bb + swz(row * 128 + c16 * 16),
                 Bg + (size_t)(n0 + row) * D_DIM + kk0 + c16 * 8);
        }
        asm volatile("cp.async.commit_group;" ::: "memory");
    };

    auto compute = [&](int s) {
        const uint32_t ab = sb + s * STG_BYTES;
        const uint32_t bb = ab + 16384;
        const int arow = lane & 15, akh = lane >> 4;
        const int brow = (lane & 7) + ((lane >> 4) << 3);
        const int bkh  = (lane >> 3) & 1;
#pragma unroll
        for (int ks = 0; ks < 4; ++ks) {
            uint32_t af[4][4], bf[2][4];
#pragma unroll
            for (int mi = 0; mi < 4; ++mi)
                ldsm_x4(af[mi], ab + swz((wm + mi * 16 + arow) * 128 +
                                         (ks * 2 + akh) * 16));
#pragma unroll
            for (int nj = 0; nj < 2; ++nj)
                ldsm_x4(bf[nj], bb + swz((wn + nj * 16 + brow) * 128 +
                                         (ks * 2 + bkh) * 16));
#pragma unroll
            for (int mi = 0; mi < 4; ++mi)
#pragma unroll
                for (int ni = 0; ni < 4; ++ni)
                    mma16816(acc[mi][ni], af[mi],
                             bf[ni >> 1][(ni & 1) * 2], bf[ni >> 1][(ni & 1) * 2 + 1]);
        }
    };

    stage(0, 0);
    stage(1, 1);
    for (int c = 0; c < NCHUNK; ++c) {
        if (c + 1 < NCHUNK)
            asm volatile("cp.async.wait_group 1;" ::: "memory");
        else
            asm volatile("cp.async.wait_group 0;" ::: "memory");
        __syncthreads();
        compute(c % 3);
        if (c + 2 < NCHUNK) stage((c + 2) % 3, c + 2);
    }

    const int qr = lane >> 2, qc = (lane & 3) * 2;
#pragma unroll
    for (int mi = 0; mi < 4; ++mi) {
        const int m = m0 + wm + mi * 16 + qr;
        float* __restrict__ rowA  = gA + (size_t)m * RDIMP;
        float* __restrict__ rowC  = gC + (size_t)m * RDIMP - RDIM;
        float* __restrict__ rowA8 = rowA + 8 * RDIMP;
        float* __restrict__ rowC8 = rowC + 8 * RDIMP;
#pragma unroll
        for (int ni = 0; ni < 4; ++ni) {
            const int n = n0 + wn + ni * 8 + qc;
            if (n >= NEXT) continue;
            float2 v0 = make_float2(acc[mi][ni][0], acc[mi][ni][1]);
            float2 v1 = make_float2(acc[mi][ni][2], acc[mi][ni][3]);
            if (n < RDIM) {
                *reinterpret_cast<float2*>(&rowA[n])  = v0;
                *reinterpret_cast<float2*>(&rowA8[n]) = v1;
            } else {
                *reinterpret_cast<float2*>(&rowC[n])  = v0;
                *reinterpret_cast<float2*>(&rowC8[n]) = v1;
            }
        }
    }
    // release: all stores visible, then bump completion counter for m-tile
    __threadfence();
    __syncthreads();
    if (t == 0) atomicAdd(&g_mtile[my], 1);
}

__device__ void do_pair_item(int b, int i,
                             const float* __restrict__ b2p,
                             float* __restrict__ pred,
                             float* __restrict__ pos,
                             float* __restrict__ h,
                             float (*sred)[NREL]) {
    const int t = threadIdx.x;
    const int lane = t & 31, wid = t >> 5;
    const bool has2 = (t < NCH4 - 256);
    const int q1 = t + 256;
    const bool q1full = has2 && (q1 < NCH4 - 1);
    const float4 z4 = make_float4(0.f, 0.f, 0.f, 0.f);

    const int jstart = max(0, i - KWIN);
    const int jend   = min(L_DIM - 1, i + KWIN);
    const int cnt    = jend - jstart + 1;
    const int off    = pair_offset(i);

    // acquire: wait for the m-tiles covering rows [b*512+jstart, b*512+jend]
    {
        const int mt0 = (b * L_DIM + jstart) >> 7;
        const int mt1 = (b * L_DIM + jend) >> 7;
        if (t == 0) {
            while (*(volatile int*)&g_mtile[mt0] < 25) __nanosleep(200);
            if (mt1 != mt0)
                while (*(volatile int*)&g_mtile[mt1] < 25) __nanosleep(200);
            __threadfence();
        }
        __syncthreads();
    }

    const float4* A4 = (const float4*)(g_A + ((size_t)b * L_DIM + i) * RDIMP);
    const float4* W4 = (const float4*)g_W2p;
    float4 a0 = A4[t],  a1 = has2 ? A4[q1] : z4;
    float4 w0 = W4[t],  w1 = has2 ? W4[q1] : z4;

    const float4* C4 = (const float4*)(g_C + ((size_t)b * L_DIM + jstart) * RDIMP);
    const float4* E4 = (const float4*)(g_E2 + (size_t)(jstart - i + KWIN) * RDIMP);
    float* Hbase = h + ((size_t)b * NPAIR + off) * RDIM;

    float4 ca0 = C4[t], ea0 = E4[t];
    float4 ca1 = has2 ? C4[q1] : z4;
    float4 ea1 = has2 ? E4[q1] : z4;

    for (int jj = 0; jj < cnt; ++jj) {
        const float4* Cn = C4 + NCH4;
        const float4* En = E4 + NCH4;
        float4 cb0 = ca0, cb1 = ca1, eb0 = ea0, eb1 = ea1;
        if (jj + 1 < cnt) {
            cb0 = Cn[t]; eb0 = En[t];
            if (has2) { cb1 = Cn[q1]; eb1 = En[q1]; }
        }

        float4 v0, v1;
        v0.x = fmaxf(a0.x + ca0.x + ea0.x, 0.f);
        v0.y = fmaxf(a0.y + ca0.y + ea0.y, 0.f);
        v0.z = fmaxf(a0.z + ca0.z + ea0.z, 0.f);
        v0.w = fmaxf(a0.w + ca0.w + ea0.w, 0.f);
        v1.x = fmaxf(a1.x + ca1.x + ea1.x, 0.f);
        v1.y = fmaxf(a1.y + ca1.y + ea1.y, 0.f);
        v1.z = fmaxf(a1.z + ca1.z + ea1.z, 0.f);
        v1.w = fmaxf(a1.w + ca1.w + ea1.w, 0.f);

        float* Hr = Hbase + (size_t)jj * RDIM;
        const bool aligned = (((off + jj) & 1) == 0);
        if (aligned) {
            __stwt((float4*)(Hr + 4 * t), v0);
            if (has2) {
                if (q1full) __stwt((float4*)(Hr + 4 * q1), v1);
                else        __stwt((float2*)(Hr + 4 * q1), make_float2(v1.x, v1.y));
            }
        } else {
            float nx0 = __shfl_down_sync(0xffffffffu, v0.x, 1);
            float ny0 = __shfl_down_sync(0xffffffffu, v0.y, 1);
            float nx1 = __shfl_down_sync(0xffffffffu, v1.x, 1);
            float ny1 = __shfl_down_sync(0xffffffffu, v1.y, 1);
            if (lane == 0)
                __stwt((float2*)(Hr + 4 * t), make_float2(v0.x, v0.y));
            if (lane < 31)
                __stwt((float4*)(Hr + 4 * t + 2), make_float4(v0.z, v0.w, nx0, ny0));
            else
                __stwt((float2*)(Hr + 4 * t + 2), make_float2(v0.z, v0.w));
            if (has2) {
                if (lane == 0)
                    __stwt((float2*)(Hr + 4 * q1), make_float2(v1.x, v1.y));
                if (q1full) {
                    if (lane < 31)
                        __stwt((float4*)(Hr + 4 * q1 + 2), make_float4(v1.z, v1.w, nx1, ny1));
                    else
                        __stwt((float2*)(Hr + 4 * q1 + 2), make_float2(v1.z, v1.w));
                }
            }
        }

        float acc = v0.x * w0.x + v0.y * w0.y;
        acc = fmaf(v0.z, w0.z, acc); acc = fmaf(v0.w, w0.w, acc);
        acc = fmaf(v1.x, w1.x, acc); acc = fmaf(v1.y, w1.y, acc);
        acc = fmaf(v1.z, w1.z, acc); acc = fmaf(v1.w, w1.w, acc);
#pragma unroll
        for (int s = 16; s; s >>= 1) acc += __shfl_down_sync(0xffffffffu, acc, s);
        if (lane == 0) sred[wid][jj] = acc;

        C4 = Cn; E4 = En;
        ca0 = cb0; ca1 = cb1; ea0 = eb0; ea1 = eb1;
    }
    __syncthreads();
    if (t < cnt) {
        float v = 0.f;
#pragma unroll
        for (int w = 0; w < 8; ++w) v += sred[w][t];
        pred[(size_t)b * NPAIR + off + t] = v + b2p[0];
    }
    if (b == 0 && t < cnt) {
        int p = off + t;
        pos[2 * p]     = (float)(i + 1);
        pos[2 * p + 1] = (float)(jstart + t + 1);
    }
}

__global__ __launch_bounds__(256, 2) void k_fused(const float* __restrict__ b2p,
                                                  float* __restrict__ pred,
                                                  float* __restrict__ pos,
                                                  float* __restrict__ h) {
    extern __shared__ char smem[];
    __shared__ int s_item;
    __shared__ float sred[8][NREL];

    for (;;) {
        if (threadIdx.x == 0) s_item = atomicAdd(&g_next, 1);
        __syncthreads();
        const int item = s_item;
        if (item >= N_ITEMS) break;
        if (item < N_MMA_ITEMS) {
            do_mma_tile(item / 25, item % 25, smem);   // m-major: tile 0 first
        } else {
            const int p = item - N_MMA_ITEMS;
            do_pair_item(p >> 9, p & (L_DIM - 1), b2p, pred, pos, h, sred);
        }
        __syncthreads();
    }
}

// ---------------------------------------------------------------------------
extern "C" void kernel_launch(void* const* d_in, const int* in_sizes, int n_in,
                              void* d_out, int out_size) {
    const float* doc     = (const float*)d_in[0];
    const float* pos_emb = (const float*)d_in[1];
    const float* W1      = (const float*)d_in[2];
    const float* b1      = (const float*)d_in[3];
    const float* W2      = (const float*)d_in[4];
    const float* b2      = (const float*)d_in[5];

    float* out  = (float*)d_out;
    float* pred = out;                                   // [4, 10642]
    float* pos  = out + (size_t)B_DIM * NPAIR;           // [10642, 2]
    float* h    = pos + 2L * NPAIR;                      // [4, 10642, 1586]

    cudaFuncSetAttribute(k_fused, cudaFuncAttributeMaxDynamicSharedMemorySize, SMEM_TOT);

    k_prep<<<PREP_X + PREP_W + PREP_E + PREP_W2, 256>>>(doc, pos_emb, W1, b1, W2);

    k_fused<<<GRID_FUSED, 256, SMEM_TOT>>>(b2, pred, pos, h);
}

// round 17
// speedup vs baseline: 1.1442x; 1.1442x over previous
#include <cuda_runtime.h>
#include <cuda_bf16.h>
#include <cstdint>

#define B_DIM 4
#define L_DIM 512
#define D_DIM 768
#define KWIN  10
#define PDIM  50
#define RDIM  1586      // 2*768 + 50
#define RDIMP 1588      // padded to 16B multiple (397 float4)
#define NREL  21
#define NPAIR 10642
#define NEXT  3172      // concatenated A|C output columns
#define NEXTP 3200      // padded to 128-multiple
#define NCHUNK 36       // 3 * 768 / 64
#define NCH4  397       // RDIMP / 4

// ------------------------- device scratch (no runtime alloc allowed) ------
__device__ __align__(16) float g_A  [B_DIM * L_DIM * RDIMP];
__device__ __align__(16) float g_C  [B_DIM * L_DIM * RDIMP];
__device__ __align__(16) float g_E2 [NREL * RDIMP];
__device__ __align__(16) float g_W2p[RDIMP];
__device__ __align__(16) __nv_bfloat16 g_Xhi[B_DIM * L_DIM * D_DIM];
__device__ __align__(16) __nv_bfloat16 g_Xlo[B_DIM * L_DIM * D_DIM];
__device__ __align__(16) __nv_bfloat16 g_Bhi[NEXTP * D_DIM];
__device__ __align__(16) __nv_bfloat16 g_Blo[NEXTP * D_DIM];

// ------------------------- helpers ----------------------------------------
__device__ __forceinline__ uint32_t smem_u32(const void* p) {
    uint32_t a;
    asm("{ .reg .u64 t; cvta.to.shared.u64 t, %1; cvt.u32.u64 %0, t; }" : "=r"(a) : "l"(p));
    return a;
}
__device__ __forceinline__ uint32_t swz(uint32_t b) { return b ^ ((b >> 3) & 0x70); }

__device__ __forceinline__ void cp16(uint32_t saddr, const void* gaddr) {
    asm volatile("cp.async.cg.shared.global [%0], [%1], 16;" :: "r"(saddr), "l"(gaddr));
}
__device__ __forceinline__ void ldsm_x4(uint32_t* r, uint32_t addr) {
    asm volatile("ldmatrix.sync.aligned.m8n8.x4.shared.b16 {%0,%1,%2,%3}, [%4];"
                 : "=r"(r[0]), "=r"(r[1]), "=r"(r[2]), "=r"(r[3]) : "r"(addr));
}
__device__ __forceinline__ void mma16816(float* d, const uint32_t* a, uint32_t b0, uint32_t b1) {
    asm volatile(
        "mma.sync.aligned.m16n8k16.row.col.f32.bf16.bf16.f32 "
        "{%0,%1,%2,%3}, {%4,%5,%6,%7}, {%8,%9}, {%0,%1,%2,%3};"
        : "+f"(d[0]), "+f"(d[1]), "+f"(d[2]), "+f"(d[3])
        : "r"(a[0]), "r"(a[1]), "r"(a[2]), "r"(a[3]), "r"(b0), "r"(b1));
}

__device__ __forceinline__ int pair_offset(int i) {
    if (i <= KWIN) return i * (KWIN + 1) + (i * (i - 1)) / 2;
    int off = 155 + (i - KWIN) * (2 * KWIN + 1);
    if (i <= L_DIM - KWIN) return off;
    int d = i - (L_DIM - KWIN);
    return off - (d * (d + 1)) / 2;
}

// ------------------------- fused precompute --------------------------------
#define PREP_X  1536
#define PREP_W  2400
#define PREP_E  147
#define PREP_W2 7
__global__ __launch_bounds__(256) void k_prep(const float* __restrict__ doc,
                                              const float* __restrict__ pos_emb,
                                              const float* __restrict__ W1,
                                              const float* __restrict__ b1,
                                              const float* __restrict__ W2) {
    const int bid = blockIdx.x;
    const int t = threadIdx.x;

    if (bid < PREP_X) {
        int idx = bid * 256 + t;       // per float4
        float4 v = reinterpret_cast<const float4*>(doc)[idx];
        __nv_bfloat16 h0 = __float2bfloat16_rn(v.x);
        __nv_bfloat16 h1 = __float2bfloat16_rn(v.y);
        __nv_bfloat16 h2 = __float2bfloat16_rn(v.z);
        __nv_bfloat16 h3 = __float2bfloat16_rn(v.w);
        __nv_bfloat162 hp0 = __nv_bfloat162(h0, h1), hp1 = __nv_bfloat162(h2, h3);
        __nv_bfloat162 lp0 = __nv_bfloat162(__float2bfloat16_rn(v.x - __bfloat162float(h0)),
                                            __float2bfloat16_rn(v.y - __bfloat162float(h1)));
        __nv_bfloat162 lp1 = __nv_bfloat162(__float2bfloat16_rn(v.z - __bfloat162float(h2)),
                                            __float2bfloat16_rn(v.w - __bfloat162float(h3)));
        reinterpret_cast<__nv_bfloat162*>(g_Xhi)[idx * 2]     = hp0;
        reinterpret_cast<__nv_bfloat162*>(g_Xhi)[idx * 2 + 1] = hp1;
        reinterpret_cast<__nv_bfloat162*>(g_Xlo)[idx * 2]     = lp0;
        reinterpret_cast<__nv_bfloat162*>(g_Xlo)[idx * 2 + 1] = lp1;
    } else if (bid < PREP_X + PREP_W) {
        __shared__ float s[32][33];
        int b2i = bid - PREP_X;
        int n0 = (b2i % 100) * 32, k0 = (b2i / 100) * 32;
        int tx = t & 31, ty = t >> 5;   // 32 x 8
#pragma unroll
        for (int r = 0; r < 4; ++r) {
            int kk = k0 + ty + r * 8;
            int nn = n0 + tx;
            float v = 0.f;
            if (nn < NEXT) {
                int col = nn < RDIM ? nn : nn - RDIM;
                int row = kk + (nn < RDIM ? 0 : D_DIM);
                v = W1[(size_t)row * RDIM + col];
            }
            s[ty + r * 8][tx] = v;
        }
        __syncthreads();
#pragma unroll
        for (int r = 0; r < 4; ++r) {
            int nl = ty + r * 8;
            int nn = n0 + nl;
            float v = s[tx][nl];
            __nv_bfloat16 h = __float2bfloat16_rn(v);
            __nv_bfloat16 l = __float2bfloat16_rn(v - __bfloat162float(h));
            g_Bhi[(size_t)nn * D_DIM + k0 + tx] = h;
            g_Blo[(size_t)nn * D_DIM + k0 + tx] = l;
        }
    } else if (bid < PREP_X + PREP_W + PREP_E) {
        __shared__ float sM[PDIM];
        int b3i = bid - PREP_X - PREP_W;       // 147 blocks
        int u  = b3i % NREL;
        int r0 = (b3i / NREL) * 256;
        if (t < PDIM) {
            float acc = 0.f;
#pragma unroll
            for (int v = 0; v < NREL; ++v) {
                float w = (float)(L_DIM - abs(v - KWIN));
                float d = (float)(u - v);
                acc += w * expf(-d * d) * pos_emb[v * PDIM + t];
            }
            sM[t] = acc;
        }
        __syncthreads();
        int r = r0 + t;
        if (r < RDIM) {
            float acc = b1[r];
#pragma unroll
            for (int p = 0; p < PDIM; ++p)
                acc += sM[p] * W1[(size_t)(2 * D_DIM + p) * RDIM + r];
            g_E2[u * RDIMP + r] = acc;
        }
    } else {
        int idx = (bid - PREP_X - PREP_W - PREP_E) * 256 + t;
        if (idx < RDIMP) g_W2p[idx] = (idx < RDIM) ? W2[idx] : 0.f;
    }
}

// ------------------------- mma.sync GEMM v2 ---------------------------------
// 128 threads, 4 warps in 2x2; each warp computes a 64x64 output tile
// (acc 128 regs). Per-ks ldsm drops from 192B/HMMA to 128B/HMMA.
#define STG_BYTES 32768                // A(16K) + B(16K) per stage
#define SMEM_TOT (3 * STG_BYTES)

__global__ __launch_bounds__(128) void k_mma(float* __restrict__ gA,
                                             float* __restrict__ gC) {
    extern __shared__ char smem[];
    const uint32_t sb = smem_u32(smem);
    const int t = threadIdx.x, w = t >> 5, lane = t & 31;
    const int n0 = blockIdx.x * 128;    // grid (25, 16)
    const int m0 = blockIdx.y * 128;
    const int wm = (w >> 1) * 64;       // 2x2 warp layout
    const int wn = (w & 1) * 64;

    float acc[4][8][4] = {};

    auto stage = [&](int s, int c) {
        const int seg = c / 12;
        const int kk0 = (c % 12) * 64;
        const __nv_bfloat16* Ag = (seg == 2) ? g_Xlo : g_Xhi;
        const __nv_bfloat16* Bg = (seg == 1) ? g_Blo : g_Bhi;
        const uint32_t ab = sb + s * STG_BYTES;
        const uint32_t bb = ab + 16384;
#pragma unroll
        for (int it = 0; it < 8; ++it) {
            int idx = it * 128 + t;
            int row = idx >> 3, c16 = idx & 7;
            cp16(ab + swz(row * 128 + c16 * 16),
                 Ag + (size_t)(m0 + row) * D_DIM + kk0 + c16 * 8);
        }
#pragma unroll
        for (int it = 0; it < 8; ++it) {
            int idx = it * 128 + t;
            int row = idx >> 3, c16 = idx & 7;
            cp16(bb + swz(row * 128 + c16 * 16),
                 Bg + (size_t)(n0 + row) * D_DIM + kk0 + c16 * 8);
        }
        asm volatile("cp.async.commit_group;" ::: "memory");
    };

    auto compute = [&](int s) {
        const uint32_t ab = sb + s * STG_BYTES;
        const uint32_t bb = ab + 16384;
        const int arow = lane & 15, akh = lane >> 4;
        const int brow = (lane & 7) + ((lane >> 4) << 3);
        const int bkh  = (lane >> 3) & 1;
#pragma unroll
        for (int ks = 0; ks < 4; ++ks) {
            uint32_t af[4][4], bf[4][4];
#pragma unroll
            for (int mi = 0; mi < 4; ++mi)
                ldsm_x4(af[mi], ab + swz((wm + mi * 16 + arow) * 128 +
                                         (ks * 2 + akh) * 16));
#pragma unroll
            for (int nj = 0; nj < 4; ++nj)
                ldsm_x4(bf[nj], bb + swz((wn + nj * 16 + brow) * 128 +
                                         (ks * 2 + bkh) * 16));
#pragma unroll
            for (int mi = 0; mi < 4; ++mi)
#pragma unroll
                for (int ni = 0; ni < 8; ++ni)
                    mma16816(acc[mi][ni], af[mi],
                             bf[ni >> 1][(ni & 1) * 2], bf[ni >> 1][(ni & 1) * 2 + 1]);
        }
    };

    stage(0, 0);
    stage(1, 1);
    for (int c = 0; c < NCHUNK; ++c) {
        if (c + 1 < NCHUNK)
            asm volatile("cp.async.wait_group 1;" ::: "memory");
        else
            asm volatile("cp.async.wait_group 0;" ::: "memory");
        __syncthreads();
        compute(c % 3);
        if (c + 2 < NCHUNK) stage((c + 2) % 3, c + 2);
    }

    const int qr = lane >> 2, qc = (lane & 3) * 2;
#pragma unroll
    for (int mi = 0; mi < 4; ++mi) {
        const int m = m0 + wm + mi * 16 + qr;
        float* __restrict__ rowA  = gA + (size_t)m * RDIMP;
        float* __restrict__ rowC  = gC + (size_t)m * RDIMP - RDIM;
        float* __restrict__ rowA8 = rowA + 8 * RDIMP;
        float* __restrict__ rowC8 = rowC + 8 * RDIMP;
#pragma unroll
        for (int ni = 0; ni < 8; ++ni) {
            const int n = n0 + wn + ni * 8 + qc;
            if (n >= NEXT) continue;
            float2 v0 = make_float2(acc[mi][ni][0], acc[mi][ni][1]);
            float2 v1 = make_float2(acc[mi][ni][2], acc[mi][ni][3]);
            if (n < RDIM) {
                *reinterpret_cast<float2*>(&rowA[n])  = v0;
                *reinterpret_cast<float2*>(&rowA8[n]) = v1;
            } else {
                *reinterpret_cast<float2*>(&rowC[n])  = v0;
                *reinterpret_cast<float2*>(&rowC8[n]) = v1;
            }
        }
    }
}

// ------------------------- pair pass (R13-exact) ----------------------------
__global__ __launch_bounds__(256) void k_pair(const float* __restrict__ b2p,
                                              float* __restrict__ pred,
                                              float* __restrict__ pos,
                                              float* __restrict__ h) {
    __shared__ float sred[8][NREL];
    const int b = blockIdx.x >> 9;
    const int i = blockIdx.x & (L_DIM - 1);
    const int t = threadIdx.x;
    const int lane = t & 31, wid = t >> 5;
    const bool has2 = (t < NCH4 - 256);     // t < 141: owns second chunk t+256
    const int q1 = t + 256;
    const bool q1full = has2 && (q1 < NCH4 - 1);   // t < 140
    const float4 z4 = make_float4(0.f, 0.f, 0.f, 0.f);

    const float4* A4 = (const float4*)(g_A + ((size_t)b * L_DIM + i) * RDIMP);
    const float4* W4 = (const float4*)g_W2p;
    float4 a0 = A4[t],  a1 = has2 ? A4[q1] : z4;
    float4 w0 = W4[t],  w1 = has2 ? W4[q1] : z4;

    const int jstart = max(0, i - KWIN);
    const int jend   = min(L_DIM - 1, i + KWIN);
    const int cnt    = jend - jstart + 1;
    const int off    = pair_offset(i);

    const float4* C4 = (const float4*)(g_C + ((size_t)b * L_DIM + jstart) * RDIMP);
    const float4* E4 = (const float4*)(g_E2 + (size_t)(jstart - i + KWIN) * RDIMP);
    float* Hbase = h + ((size_t)b * NPAIR + off) * RDIM;

    // prefetch pair 0
    float4 ca0 = C4[t], ea0 = E4[t];
    float4 ca1 = has2 ? C4[q1] : z4;
    float4 ea1 = has2 ? E4[q1] : z4;

    for (int jj = 0; jj < cnt; ++jj) {
        const float4* Cn = C4 + NCH4;
        const float4* En = E4 + NCH4;
        float4 cb0 = ca0, cb1 = ca1, eb0 = ea0, eb1 = ea1;
        if (jj + 1 < cnt) {
            cb0 = Cn[t]; eb0 = En[t];
            if (has2) { cb1 = Cn[q1]; eb1 = En[q1]; }
        }

        float4 v0, v1;
        v0.x = fmaxf(a0.x + ca0.x + ea0.x, 0.f);
        v0.y = fmaxf(a0.y + ca0.y + ea0.y, 0.f);
        v0.z = fmaxf(a0.z + ca0.z + ea0.z, 0.f);
        v0.w = fmaxf(a0.w + ca0.w + ea0.w, 0.f);
        v1.x = fmaxf(a1.x + ca1.x + ea1.x, 0.f);
        v1.y = fmaxf(a1.y + ca1.y + ea1.y, 0.f);
        v1.z = fmaxf(a1.z + ca1.z + ea1.z, 0.f);
        v1.w = fmaxf(a1.w + ca1.w + ea1.w, 0.f);

        float* Hr = Hbase + (size_t)jj * RDIM;
        const bool aligned = (((off + jj) & 1) == 0);   // h row 16B-aligned iff p even
        if (aligned) {
            __stwt((float4*)(Hr + 4 * t), v0);
            if (has2) {
                if (q1full) __stwt((float4*)(Hr + 4 * q1), v1);
                else        __stwt((float2*)(Hr + 4 * q1), make_float2(v1.x, v1.y));
            }
        } else {
            // row base % 16 == 8: shift by 2 elements via shuffle; head/tail float2.
            float nx0 = __shfl_down_sync(0xffffffffu, v0.x, 1);
            float ny0 = __shfl_down_sync(0xffffffffu, v0.y, 1);
            float nx1 = __shfl_down_sync(0xffffffffu, v1.x, 1);
            float ny1 = __shfl_down_sync(0xffffffffu, v1.y, 1);
            if (lane == 0)
                __stwt((float2*)(Hr + 4 * t), make_float2(v0.x, v0.y));
            if (lane < 31)
                __stwt((float4*)(Hr + 4 * t + 2), make_float4(v0.z, v0.w, nx0, ny0));
            else
                __stwt((float2*)(Hr + 4 * t + 2), make_float2(v0.z, v0.w));
            if (has2) {
                if (lane == 0)
                    __stwt((float2*)(Hr + 4 * q1), make_float2(v1.x, v1.y));
                if (q1full) {
                    if (lane < 31)
                        __stwt((float4*)(Hr + 4 * q1 + 2), make_float4(v1.z, v1.w, nx1, ny1));
                    else
                        __stwt((float2*)(Hr + 4 * q1 + 2), make_float2(v1.z, v1.w));
                }
            }
        }

        float acc = v0.x * w0.x + v0.y * w0.y;
        acc = fmaf(v0.z, w0.z, acc); acc = fmaf(v0.w, w0.w, acc);
        acc = fmaf(v1.x, w1.x, acc); acc = fmaf(v1.y, w1.y, acc);
        acc = fmaf(v1.z, w1.z, acc); acc = fmaf(v1.w, w1.w, acc);
#pragma unroll
        for (int s = 16; s; s >>= 1) acc += __shfl_down_sync(0xffffffffu, acc, s);
        if (lane == 0) sred[wid][jj] = acc;

        C4 = Cn; E4 = En;
        ca0 = cb0; ca1 = cb1; ea0 = eb0; ea1 = eb1;
    }
    __syncthreads();
    if (t < cnt) {
        float v = 0.f;
#pragma unroll
        for (int w = 0; w < 8; ++w) v += sred[w][t];
        pred[(size_t)b * NPAIR + off + t] = v + b2p[0];
    }
    if (b == 0 && t < cnt) {
        int p = off + t;
        pos[2 * p]     = (float)(i + 1);
        pos[2 * p + 1] = (float)(jstart + t + 1);
    }
}

// ---------------------------------------------------------------------------
extern "C" void kernel_launch(void* const* d_in, const int* in_sizes, int n_in,
                              void* d_out, int out_size) {
    const float* doc     = (const float*)d_in[0];
    const float* pos_emb = (const float*)d_in[1];
    const float* W1      = (const float*)d_in[2];
    const float* b1      = (const float*)d_in[3];
    const float* W2      = (const float*)d_in[4];
    const float* b2      = (const float*)d_in[5];

    float* out  = (float*)d_out;
    float* pred = out;                                   // [4, 10642]
    float* pos  = out + (size_t)B_DIM * NPAIR;           // [10642, 2]
    float* h    = pos + 2L * NPAIR;                      // [4, 10642, 1586]

    float *gA = nullptr, *gC = nullptr;
    cudaGetSymbolAddress((void**)&gA, g_A);
    cudaGetSymbolAddress((void**)&gC, g_C);

    cudaFuncSetAttribute(k_mma, cudaFuncAttributeMaxDynamicSharedMemorySize, SMEM_TOT);

    k_prep<<<PREP_X + PREP_W + PREP_E + PREP_W2, 256>>>(doc, pos_emb, W1, b1, W2);

    k_mma<<<dim3(25, 16), 128, SMEM_TOT>>>(gA, gC);

    k_pair<<<B_DIM * L_DIM, 256>>>(b2, pred, pos, h);
}